// round 2
// baseline (speedup 1.0000x reference)
#include <cuda_runtime.h>
#include <math.h>

#define Bq 16
#define Tt 1024
#define Dd 512
#define Hh 8
#define HDim 64
#define CO 7
#define PRED 96
#define KK 8
#define LATENT 2048
#define NFREQ 511
#define TP (Tt + PRED)

#define RES3_OFF 0
#define LVL_OFF  (Bq*Tt*Dd)                       // 8388608
#define GROW_OFF (LVL_OFF + Bq*Tt*CO)             // 8503296
#define SEAS_OFF (GROW_OFF + Bq*(Tt+1)*Dd)        // 16900096

#define PI2 6.283185307179586476925286766559f

// ---------------- scratch (device globals; no runtime allocation) ----------
__device__ float g_twc[1024];
__device__ float g_tws[1024];
__device__ float g_Xre[(size_t)Bq*NFREQ*Dd];
__device__ float g_Xim[(size_t)Bq*NFREQ*Dd];
__device__ int   g_fr[Bq*Dd*KK];
__device__ float g_amp[Bq*Dd*KK];
__device__ float g_ph[Bq*Dd*KK];
__device__ float g_res1[(size_t)Bq*Tt*Dd];
__device__ float g_v[(size_t)Bq*Tt*Dd];
__device__ float g_smcat[(size_t)Bq*(Tt+1)*Dd];
__device__ float g_res2[(size_t)Bq*Tt*Dd];
__device__ float g_ffh[(size_t)Bq*Tt*LATENT];
__device__ float g_ffy[(size_t)Bq*Tt*Dd];
__device__ float g_gp[Bq*Tt*CO];
__device__ float g_sp[Bq*Tt*CO];

// ---------------- twiddle table ----------------
__global__ void k_twiddle() {
    int j = threadIdx.x;
    if (j < 1024) {
        double a = 2.0 * 3.14159265358979323846 * (double)j / 1024.0;
        g_twc[j] = (float)cos(a);
        g_tws[j] = (float)sin(a);
    }
}

// ---------------- DFT: X[f] = sum_t x[t] * e^{-2pi i f t / 1024}, f=1..511 --
// block: (f_tile of 8, b); 512 threads over d
__global__ void k_dft(const float* __restrict__ x) {
    __shared__ float2 tw[1024];
    int d = threadIdx.x;
    int b = blockIdx.y;
    int f0 = 1 + blockIdx.x * 8;
    for (int j = d; j < 1024; j += 512) tw[j] = make_float2(g_twc[j], g_tws[j]);
    __syncthreads();

    float re[8], im[8];
#pragma unroll
    for (int j = 0; j < 8; j++) { re[j] = 0.f; im[j] = 0.f; }

    const float* xp = x + (size_t)b * Tt * Dd + d;
    for (int t = 0; t < Tt; t++) {
        float xv = xp[(size_t)t * Dd];
#pragma unroll
        for (int j = 0; j < 8; j++) {
            int id = ((f0 + j) * t) & 1023;
            float2 w = tw[id];
            re[j] = fmaf(xv, w.x, re[j]);
            im[j] = fmaf(-xv, w.y, im[j]);
        }
    }
#pragma unroll
    for (int j = 0; j < 8; j++) {
        int f = f0 + j;
        if (f <= NFREQ) {
            size_t o = ((size_t)b * NFREQ + (f - 1)) * Dd + d;
            g_Xre[o] = re[j];
            g_Xim[o] = im[j];
        }
    }
}

// ---------------- top-K per (b, d) over 511 freqs ----------------
__global__ void k_topk() {
    int d = threadIdx.x;
    int b = blockIdx.x;
    float val[KK];
    int   idx[KK];
#pragma unroll
    for (int k = 0; k < KK; k++) { val[k] = -1.f; idx[k] = 0; }

    for (int f = 0; f < NFREQ; f++) {
        size_t o = ((size_t)b * NFREQ + f) * Dd + d;
        float re = g_Xre[o], im = g_Xim[o];
        float m = re * re + im * im;
        if (m > val[KK - 1]) {
            int p = KK - 1;
            while (p > 0 && m > val[p - 1]) {
                val[p] = val[p - 1]; idx[p] = idx[p - 1]; p--;
            }
            val[p] = m; idx[p] = f;
        }
    }
    int base = (b * Dd + d) * KK;
#pragma unroll
    for (int k = 0; k < KK; k++) {
        int f = idx[k];
        size_t o = ((size_t)b * NFREQ + f) * Dd + d;
        float re = g_Xre[o], im = g_Xim[o];
        float mag = sqrtf(re * re + im * im);
        g_fr[base + k]  = f + 1;                 // actual integer frequency bin
        g_amp[base + k] = 2.0f * mag * (1.0f / 1024.0f);
        g_ph[base + k]  = atan2f(im, re);
    }
}

// ---------------- season synthesis + res1 = res - season[:, :T] -----------
// block: (t_tile of 16, b); 512 threads over d
__global__ void k_season(const float* __restrict__ res,
                         float* __restrict__ season,
                         float* __restrict__ res1) {
    int d = threadIdx.x;
    int b = blockIdx.y;
    int t0 = blockIdx.x * 16;
    int base = (b * Dd + d) * KK;
    int fr[KK]; float am[KK], ph[KK];
#pragma unroll
    for (int k = 0; k < KK; k++) {
        fr[k] = g_fr[base + k]; am[k] = g_amp[base + k]; ph[k] = g_ph[base + k];
    }
    for (int tt = 0; tt < 16; tt++) {
        int t = t0 + tt;
        float sum = 0.f;
#pragma unroll
        for (int k = 0; k < KK; k++) {
            int id = (fr[k] * t) & 1023;
            sum += am[k] * __cosf((float)id * (PI2 / 1024.0f) + ph[k]);
        }
        season[((size_t)b * TP + t) * Dd + d] = sum;
        if (t < Tt) {
            size_t o = ((size_t)b * Tt + t) * Dd + d;
            res1[o] = res[o] - sum;
        }
    }
}

// ---------------- SGEMM: C[M,N] = A[M,K] @ W[K,N], optional GELU ----------
// BM=128 BN=64 BK=16 TM=8 TN=4, 256 threads
template <int EPI>
__global__ void k_sgemm(const float* __restrict__ A, const float* __restrict__ W,
                        float* __restrict__ C, int M, int N, int K) {
    const int BM = 128, BN = 64, BK = 16, TM = 8, TN = 4;
    __shared__ float As[BK][BM];
    __shared__ float Bs[BK][BN];
    int tid = threadIdx.x;
    int brow = blockIdx.y * BM;
    int bcol = blockIdx.x * BN;
    int tr = (tid / 16) * TM;
    int tc = (tid % 16) * TN;
    float acc[TM][TN];
#pragma unroll
    for (int i = 0; i < TM; i++)
#pragma unroll
        for (int j = 0; j < TN; j++) acc[i][j] = 0.f;

    int a_r = tid / 4;
    int a_c = (tid % 4) * 4;
    int b_r = tid / 16;
    int b_c = (tid % 16) * 4;

    for (int k0 = 0; k0 < K; k0 += BK) {
#pragma unroll
        for (int i = 0; i < 2; i++) {
            int r = a_r + i * 64;
            int grow = brow + r;
            float4 v = make_float4(0.f, 0.f, 0.f, 0.f);
            if (grow < M) v = *(const float4*)&A[(size_t)grow * K + k0 + a_c];
            As[a_c + 0][r] = v.x; As[a_c + 1][r] = v.y;
            As[a_c + 2][r] = v.z; As[a_c + 3][r] = v.w;
        }
        float4 bv = *(const float4*)&W[(size_t)(k0 + b_r) * N + bcol + b_c];
        *(float4*)&Bs[b_r][b_c] = bv;
        __syncthreads();
#pragma unroll
        for (int kk = 0; kk < BK; kk++) {
            float ar[TM], br[TN];
#pragma unroll
            for (int i = 0; i < TM; i++) ar[i] = As[kk][tr + i];
#pragma unroll
            for (int j = 0; j < TN; j++) br[j] = Bs[kk][tc + j];
#pragma unroll
            for (int i = 0; i < TM; i++)
#pragma unroll
                for (int j = 0; j < TN; j++) acc[i][j] = fmaf(ar[i], br[j], acc[i][j]);
        }
        __syncthreads();
    }
#pragma unroll
    for (int i = 0; i < TM; i++) {
        int grow = brow + tr + i;
        if (grow >= M) break;
        float4 v;
        float* p = (float*)&v;
#pragma unroll
        for (int j = 0; j < TN; j++) {
            float x = acc[i][j];
            if (EPI == 1) x = 0.5f * x * (1.0f + erff(x * 0.70710678118654752440f));
            p[j] = x;
        }
        *(float4*)&C[(size_t)grow * N + bcol + tc] = v;
    }
}

// ---------------- growth scan: diff + EMA, writes smcat[b,1025,512] -------
__global__ void k_growth_scan(const float* __restrict__ sw,
                              const float* __restrict__ z0,
                              const float* __restrict__ v0) {
    int b = blockIdx.x;
    int hd = threadIdx.x;      // 0..511
    int h = hd >> 6;
    float w = 1.0f / (1.0f + expf(-sw[h]));
    float omw = 1.0f - w;
    float prev = z0[hd];
    float s = v0[hd];
    g_smcat[(size_t)b * (Tt + 1) * Dd + hd] = s;
    const float* vp = g_v + (size_t)b * Tt * Dd + hd;
    float* op = g_smcat + (size_t)b * (Tt + 1) * Dd + Dd + hd;
    for (int t = 0; t < Tt; t++) {
        float val = vp[(size_t)t * Dd];
        float diff = val - prev;
        prev = val;
        s = fmaf(w, s, omw * diff);
        op[(size_t)t * Dd] = s;
    }
}

// ---------------- LayerNorm over last dim (512). MODE 0: A - growth-shift, MODE 1: A + B
__device__ __forceinline__ float wred(float v) {
#pragma unroll
    for (int o = 16; o > 0; o >>= 1) v += __shfl_xor_sync(0xffffffffu, v, o);
    return v;
}

template <int MODE>
__global__ void k_ln(const float* __restrict__ A, const float* __restrict__ Bm,
                     const float* __restrict__ gg, const float* __restrict__ bb,
                     float* __restrict__ out) {
    int r = blockIdx.x;       // 0..16383
    int tid = threadIdx.x;    // 128
    const float* arow = A + (size_t)r * Dd;
    const float* brow;
    if (MODE == 0) {
        int b = r >> 10, t = r & 1023;
        brow = Bm + ((size_t)b * (Tt + 1) + t + 1) * Dd;
    } else {
        brow = Bm + (size_t)r * Dd;
    }
    int c0 = tid * 4;
    float4 a = *(const float4*)(arow + c0);
    float4 c = *(const float4*)(brow + c0);
    float x0, x1, x2, x3;
    if (MODE == 0) { x0 = a.x - c.x; x1 = a.y - c.y; x2 = a.z - c.z; x3 = a.w - c.w; }
    else           { x0 = a.x + c.x; x1 = a.y + c.y; x2 = a.z + c.z; x3 = a.w + c.w; }

    __shared__ float red[8];
    float s = x0 + x1 + x2 + x3;
    s = wred(s);
    int wid = tid >> 5, lane = tid & 31;
    if (!lane) red[wid] = s;
    __syncthreads();
    float mu = (red[0] + red[1] + red[2] + red[3]) * (1.0f / 512.0f);
    float d0 = x0 - mu, d1 = x1 - mu, d2 = x2 - mu, d3 = x3 - mu;
    float q = d0 * d0 + d1 * d1 + d2 * d2 + d3 * d3;
    q = wred(q);
    if (!lane) red[4 + wid] = q;
    __syncthreads();
    float var = (red[4] + red[5] + red[6] + red[7]) * (1.0f / 512.0f);
    float inv = rsqrtf(var + 1e-5f);
    float4 g4 = *(const float4*)(gg + c0);
    float4 b4 = *(const float4*)(bb + c0);
    float4 o4;
    o4.x = d0 * inv * g4.x + b4.x;
    o4.y = d1 * inv * g4.y + b4.y;
    o4.z = d2 * inv * g4.z + b4.z;
    o4.w = d3 * inv * g4.w + b4.w;
    *(float4*)(out + (size_t)r * Dd + c0) = o4;
}

// ---------------- small prediction GEMM: out[b,t,c] = A_row(b,t) . W[:,c] --
__global__ void k_pred(const float* __restrict__ A, int rows_per_b,
                       const float* __restrict__ W, float* __restrict__ out) {
    __shared__ float ws[Dd * CO];
    int tid = threadIdx.x;   // 256
    for (int i = tid; i < Dd * CO; i += 256) ws[i] = W[i];
    __syncthreads();
    int r = blockIdx.x * 256 + tid;   // 0..16383
    int b = r >> 10, t = r & 1023;
    const float* a = A + ((size_t)b * rows_per_b + t) * Dd;
    float acc[CO];
#pragma unroll
    for (int c = 0; c < CO; c++) acc[c] = 0.f;
    for (int k = 0; k < Dd; k += 4) {
        float4 av = *(const float4*)(a + k);
#pragma unroll
        for (int c = 0; c < CO; c++) {
            acc[c] = fmaf(av.x, ws[(k + 0) * CO + c], acc[c]);
            acc[c] = fmaf(av.y, ws[(k + 1) * CO + c], acc[c]);
            acc[c] = fmaf(av.z, ws[(k + 2) * CO + c], acc[c]);
            acc[c] = fmaf(av.w, ws[(k + 3) * CO + c], acc[c]);
        }
    }
    float* o = out + (size_t)r * CO;
#pragma unroll
    for (int c = 0; c < CO; c++) o[c] = acc[c];
}

// ---------------- level scan: EMA with aux ----------------
__global__ void k_level(const float* __restrict__ level,
                        const float* __restrict__ lsw,
                        const float* __restrict__ lv0,
                        float* __restrict__ out) {
    int tid = threadIdx.x;
    if (tid >= Bq * CO) return;
    int b = tid / CO, c = tid % CO;
    float w = 1.0f / (1.0f + expf(-lsw[c]));
    float omw = 1.0f - w;
    float s = lv0[c];
    float a = 0.f;
    const float* lp = level + (size_t)b * Tt * CO + c;
    const float* gp = g_gp + (size_t)b * Tt * CO + c;
    const float* sp = g_sp + (size_t)b * Tt * CO + c;
    float* op = out + (size_t)b * Tt * CO + c;
    for (int t = 0; t < Tt; t++) {
        float val = lp[t * CO] - sp[t * CO];
        s = fmaf(w, s, omw * val);
        a = w * (a + gp[t * CO]);
        op[t * CO] = s + a;
    }
}

// ---------------- GEMM wrappers that read from device-global scratch ------
__global__ void k_noop() {}

extern "C" void kernel_launch(void* const* d_in, const int* in_sizes, int n_in,
                              void* d_out, int out_size) {
    const float* res   = (const float*)d_in[0];
    const float* level = (const float*)d_in[1];
    const float* in_w  = (const float*)d_in[2];
    const float* out_w = (const float*)d_in[3];
    const float* z0    = (const float*)d_in[4];
    const float* gsw   = (const float*)d_in[5];
    const float* gv0   = (const float*)d_in[6];
    const float* ffw1  = (const float*)d_in[7];
    const float* ffw2  = (const float*)d_in[8];
    const float* n1g   = (const float*)d_in[9];
    const float* n1b   = (const float*)d_in[10];
    const float* n2g   = (const float*)d_in[11];
    const float* n2b   = (const float*)d_in[12];
    const float* gpw   = (const float*)d_in[13];
    const float* spw   = (const float*)d_in[14];
    const float* lsw   = (const float*)d_in[15];
    const float* lv0   = (const float*)d_in[16];
    float* out = (float*)d_out;

    // resolve device-global scratch addresses
    float *p_res1, *p_v, *p_smcat, *p_res2, *p_ffh, *p_ffy, *p_gp, *p_sp;
    cudaGetSymbolAddress((void**)&p_res1,  g_res1);
    cudaGetSymbolAddress((void**)&p_v,     g_v);
    cudaGetSymbolAddress((void**)&p_smcat, g_smcat);
    cudaGetSymbolAddress((void**)&p_res2,  g_res2);
    cudaGetSymbolAddress((void**)&p_ffh,   g_ffh);
    cudaGetSymbolAddress((void**)&p_ffy,   g_ffy);
    cudaGetSymbolAddress((void**)&p_gp,    g_gp);
    cudaGetSymbolAddress((void**)&p_sp,    g_sp);

    // 1. twiddles
    k_twiddle<<<1, 1024>>>();
    // 2. DFT of res over time axis
    k_dft<<<dim3(64, Bq), 512>>>(res);
    // 3. top-K frequencies per (b, d)
    k_topk<<<Bq, 512>>>();
    // 4. season synthesis (+ res1) -> d_out season region
    k_season<<<dim3(TP / 16, Bq), 512>>>(res, out + SEAS_OFF, p_res1);
    // 5. v = res1 @ in_proj_w
    k_sgemm<0><<<dim3(Dd / 64, (Bq * Tt + 127) / 128), 256>>>(p_res1, in_w, p_v,
                                                              Bq * Tt, Dd, Dd);
    // 6. growth scan (diff + EMA) -> smcat [b, 1025, 512]
    k_growth_scan<<<Bq, 512>>>(gsw, z0, gv0);
    // 7. growth = smcat @ out_proj_w -> d_out growth region
    k_sgemm<0><<<dim3(Dd / 64, (Bq * (Tt + 1) + 127) / 128), 256>>>(
        p_smcat, out_w, out + GROW_OFF, Bq * (Tt + 1), Dd, Dd);
    // 8. res2 = LN(res1 - growth[:,1:])
    k_ln<0><<<Bq * Tt, 128>>>(p_res1, out + GROW_OFF, n1g, n1b, p_res2);
    // 9. ffh = gelu(res2 @ ff_w1)
    k_sgemm<1><<<dim3(LATENT / 64, (Bq * Tt + 127) / 128), 256>>>(
        p_res2, ffw1, p_ffh, Bq * Tt, LATENT, Dd);
    // 10. ffy = ffh @ ff_w2
    k_sgemm<0><<<dim3(Dd / 64, (Bq * Tt + 127) / 128), 256>>>(
        p_ffh, ffw2, p_ffy, Bq * Tt, Dd, LATENT);
    // 11. res3 = LN(res2 + ffy) -> d_out res3 region
    k_ln<1><<<Bq * Tt, 128>>>(p_res2, p_ffy, n2g, n2b, out + RES3_OFF);
    // 12. g = growth[:, :-1] @ growth_pred_w
    k_pred<<<(Bq * Tt) / 256, 256>>>(out + GROW_OFF, Tt + 1, gpw, p_gp);
    // 13. s = season[:, :T] @ season_pred_w
    k_pred<<<(Bq * Tt) / 256, 256>>>(out + SEAS_OFF, TP, spw, p_sp);
    // 14. level scan -> d_out level region
    k_level<<<1, 128>>>(level, lsw, lv0, out + LVL_OFF);
}

// round 4
// speedup vs baseline: 1.4104x; 1.4104x over previous
#include <cuda_runtime.h>
#include <math.h>
#include <stdint.h>

#define Bq 16
#define Tt 1024
#define Dd 512
#define CO 7
#define PRED 96
#define KK 8
#define LATENT 2048
#define NFREQ 511
#define TP (Tt + PRED)

#define RES3_OFF 0
#define LVL_OFF  (Bq*Tt*Dd)
#define GROW_OFF (LVL_OFF + Bq*Tt*CO)
#define SEAS_OFF (GROW_OFF + Bq*(Tt+1)*Dd)

#define PI2 6.283185307179586476925286766559f

// ---------------- scratch ----------------
__device__ float g_twc[1024];
__device__ float g_tws[1024];
__device__ float g_Xre[(size_t)Bq*NFREQ*Dd];
__device__ float g_Xim[(size_t)Bq*NFREQ*Dd];
__device__ int   g_fr[Bq*Dd*KK];
__device__ float g_amp[Bq*Dd*KK];
__device__ float g_ph[Bq*Dd*KK];
__device__ float g_res1[(size_t)Bq*Tt*Dd];
__device__ float g_v[(size_t)Bq*Tt*Dd];
__device__ float g_smcat[(size_t)Bq*(Tt+1)*Dd];
__device__ float g_res2[(size_t)Bq*Tt*Dd];
__device__ float g_ffh[(size_t)Bq*Tt*LATENT];
__device__ float g_ffy[(size_t)Bq*Tt*Dd];
__device__ float g_gp[Bq*Tt*CO];
__device__ float g_sp[Bq*Tt*CO];

// ---------------- twiddle table ----------------
__global__ void k_twiddle() {
    int j = threadIdx.x;
    if (j < 1024) {
        double a = 2.0 * 3.14159265358979323846 * (double)j / 1024.0;
        g_twc[j] = (float)cos(a);
        g_tws[j] = (float)sin(a);
    }
}

// ---------------- DFT (fp32; keeps top-k selection reference-exact) -------
__global__ void k_dft(const float* __restrict__ x) {
    __shared__ float2 tw[1024];
    int d = threadIdx.x;
    int b = blockIdx.y;
    int f0 = 1 + blockIdx.x * 8;
    for (int j = d; j < 1024; j += 512) tw[j] = make_float2(g_twc[j], g_tws[j]);
    __syncthreads();

    float re[8], im[8];
#pragma unroll
    for (int j = 0; j < 8; j++) { re[j] = 0.f; im[j] = 0.f; }

    const float* xp = x + (size_t)b * Tt * Dd + d;
    for (int t = 0; t < Tt; t++) {
        float xv = xp[(size_t)t * Dd];
#pragma unroll
        for (int j = 0; j < 8; j++) {
            int id = ((f0 + j) * t) & 1023;
            float2 w = tw[id];
            re[j] = fmaf(xv, w.x, re[j]);
            im[j] = fmaf(-xv, w.y, im[j]);
        }
    }
#pragma unroll
    for (int j = 0; j < 8; j++) {
        int f = f0 + j;
        if (f <= NFREQ) {
            size_t o = ((size_t)b * NFREQ + (f - 1)) * Dd + d;
            g_Xre[o] = re[j];
            g_Xim[o] = im[j];
        }
    }
}

// ---------------- top-K per (b, d) ----------------
__global__ void k_topk() {
    int d = threadIdx.x;
    int b = blockIdx.x;
    float val[KK];
    int   idx[KK];
#pragma unroll
    for (int k = 0; k < KK; k++) { val[k] = -1.f; idx[k] = 0; }

    for (int f = 0; f < NFREQ; f++) {
        size_t o = ((size_t)b * NFREQ + f) * Dd + d;
        float re = g_Xre[o], im = g_Xim[o];
        float m = re * re + im * im;
        if (m > val[KK - 1]) {
            int p = KK - 1;
            while (p > 0 && m > val[p - 1]) {
                val[p] = val[p - 1]; idx[p] = idx[p - 1]; p--;
            }
            val[p] = m; idx[p] = f;
        }
    }
    int base = (b * Dd + d) * KK;
#pragma unroll
    for (int k = 0; k < KK; k++) {
        int f = idx[k];
        size_t o = ((size_t)b * NFREQ + f) * Dd + d;
        float re = g_Xre[o], im = g_Xim[o];
        float mag = sqrtf(re * re + im * im);
        g_fr[base + k]  = f + 1;
        g_amp[base + k] = 2.0f * mag * (1.0f / 1024.0f);
        g_ph[base + k]  = atan2f(im, re);
    }
}

// ---------------- season synthesis + res1 ----------------
__global__ void k_season(const float* __restrict__ res,
                         float* __restrict__ season,
                         float* __restrict__ res1) {
    int d = threadIdx.x;
    int b = blockIdx.y;
    int t0 = blockIdx.x * 16;
    int base = (b * Dd + d) * KK;
    int fr[KK]; float am[KK], ph[KK];
#pragma unroll
    for (int k = 0; k < KK; k++) {
        fr[k] = g_fr[base + k]; am[k] = g_amp[base + k]; ph[k] = g_ph[base + k];
    }
    for (int tt = 0; tt < 16; tt++) {
        int t = t0 + tt;
        float sum = 0.f;
#pragma unroll
        for (int k = 0; k < KK; k++) {
            int id = (fr[k] * t) & 1023;
            sum += am[k] * __cosf((float)id * (PI2 / 1024.0f) + ph[k]);
        }
        season[((size_t)b * TP + t) * Dd + d] = sum;
        if (t < Tt) {
            size_t o = ((size_t)b * Tt + t) * Dd + d;
            res1[o] = res[o] - sum;
        }
    }
}

// ================= tf32 tensor-core GEMM =================
// C[M,N] = A[M,K] @ W[K,N].  BM=128 BN=128 BK=16, 256 threads (8 warps 2x4),
// warp tile 64x32 (mt 4 x nt 4 of m16n8k8).  XOR-swizzled SMEM, double buffer.
__device__ __forceinline__ uint32_t f2tf(float x) {
    uint32_t u;
    asm("cvt.rna.tf32.f32 %0, %1;" : "=r"(u) : "f"(x));
    return u;
}

template <int EPI>
__global__ __launch_bounds__(256)
void k_mma(const float* __restrict__ A, const float* __restrict__ W,
           float* __restrict__ C, int M, int N, int K) {
    const int BM = 128, BN = 128, BK = 16;
    __shared__ uint32_t As[2][BK * BM];
    __shared__ uint32_t Bs[2][BK * BN];

    int tid  = threadIdx.x;
    int lane = tid & 31;
    int warp = tid >> 5;
    int warpM = warp >> 2;          // 0..1
    int warpN = warp & 3;           // 0..3
    int brow = blockIdx.y * BM;
    int bcol = blockIdx.x * BN;

    int lr = lane >> 2;             // 0..7
    int lc = lane & 3;              // 0..3

    float acc[4][4][4];
#pragma unroll
    for (int i = 0; i < 4; i++)
#pragma unroll
        for (int j = 0; j < 4; j++)
#pragma unroll
            for (int q = 0; q < 4; q++) acc[i][j][q] = 0.f;

    // loader indices
    int a_m0 = tid >> 2;            // 0..63 (and +64)
    int a_kg = (tid & 3) * 4;       // 0,4,8,12
    int b_k0 = tid >> 5;            // 0..7 (and +8)
    int b_n0 = (tid & 31) * 4;      // 0..124

    float4 ra[2], rb[2];

    // ---- prefetch tile 0 ----
    {
        int k0 = 0;
#pragma unroll
        for (int it = 0; it < 2; it++) {
            int m = a_m0 + it * 64;
            int grow = brow + m;
            float4 v = make_float4(0.f, 0.f, 0.f, 0.f);
            if (grow < M) v = *(const float4*)&A[(size_t)grow * K + k0 + a_kg];
            ra[it] = v;
            int kr = b_k0 + it * 8;
            rb[it] = *(const float4*)&W[(size_t)(k0 + kr) * N + bcol + b_n0];
        }
#pragma unroll
        for (int it = 0; it < 2; it++) {
            int m = a_m0 + it * 64;
            const float* pv = (const float*)&ra[it];
#pragma unroll
            for (int i = 0; i < 4; i++)
                As[0][(a_kg + i) * BM + (m ^ (i << 3))] = f2tf(pv[i]);
            int kr = b_k0 + it * 8;
            int sw = (kr & 3) << 3;
            const float* pw = (const float*)&rb[it];
#pragma unroll
            for (int i = 0; i < 4; i++)
                Bs[0][kr * BN + ((b_n0 + i) ^ sw)] = f2tf(pw[i]);
        }
    }
    __syncthreads();

    int buf = 0;
    for (int k0 = 0; k0 < K; k0 += BK) {
        bool more = (k0 + BK) < K;
        if (more) {
            int kn = k0 + BK;
#pragma unroll
            for (int it = 0; it < 2; it++) {
                int m = a_m0 + it * 64;
                int grow = brow + m;
                float4 v = make_float4(0.f, 0.f, 0.f, 0.f);
                if (grow < M) v = *(const float4*)&A[(size_t)grow * K + kn + a_kg];
                ra[it] = v;
                int kr = b_k0 + it * 8;
                rb[it] = *(const float4*)&W[(size_t)(kn + kr) * N + bcol + b_n0];
            }
        }

        // ---- compute from buf ----
        const uint32_t* as = As[buf];
        const uint32_t* bs = Bs[buf];
#pragma unroll
        for (int ks = 0; ks < 2; ks++) {
            uint32_t af[4][4];
#pragma unroll
            for (int mt = 0; mt < 4; mt++) {
                int r = warpM * 64 + mt * 16 + lr;
                int sw = lc << 3;
                af[mt][0] = as[(ks * 8 + lc) * BM + (r ^ sw)];
                af[mt][1] = as[(ks * 8 + lc) * BM + ((r + 8) ^ sw)];
                af[mt][2] = as[(ks * 8 + lc + 4) * BM + (r ^ sw)];
                af[mt][3] = as[(ks * 8 + lc + 4) * BM + ((r + 8) ^ sw)];
            }
            uint32_t bf[4][2];
#pragma unroll
            for (int nt = 0; nt < 4; nt++) {
                int n0 = warpN * 32 + nt * 8 + lr;
                int sw = lc << 3;
                bf[nt][0] = bs[(ks * 8 + lc) * BN + (n0 ^ sw)];
                bf[nt][1] = bs[(ks * 8 + lc + 4) * BN + (n0 ^ sw)];
            }
#pragma unroll
            for (int mt = 0; mt < 4; mt++)
#pragma unroll
                for (int nt = 0; nt < 4; nt++) {
                    asm volatile(
                        "mma.sync.aligned.m16n8k8.row.col.f32.tf32.tf32.f32 "
                        "{%0,%1,%2,%3}, {%4,%5,%6,%7}, {%8,%9}, {%0,%1,%2,%3};"
                        : "+f"(acc[mt][nt][0]), "+f"(acc[mt][nt][1]),
                          "+f"(acc[mt][nt][2]), "+f"(acc[mt][nt][3])
                        : "r"(af[mt][0]), "r"(af[mt][1]), "r"(af[mt][2]), "r"(af[mt][3]),
                          "r"(bf[nt][0]), "r"(bf[nt][1]));
                }
        }

        if (more) {
            int nb = buf ^ 1;
#pragma unroll
            for (int it = 0; it < 2; it++) {
                int m = a_m0 + it * 64;
                const float* pv = (const float*)&ra[it];
#pragma unroll
                for (int i = 0; i < 4; i++)
                    As[nb][(a_kg + i) * BM + (m ^ (i << 3))] = f2tf(pv[i]);
                int kr = b_k0 + it * 8;
                int sw = (kr & 3) << 3;
                const float* pw = (const float*)&rb[it];
#pragma unroll
                for (int i = 0; i < 4; i++)
                    Bs[nb][kr * BN + ((b_n0 + i) ^ sw)] = f2tf(pw[i]);
            }
        }
        __syncthreads();
        buf ^= 1;
    }

    // ---- epilogue ----
#pragma unroll
    for (int mt = 0; mt < 4; mt++) {
        int r0 = brow + warpM * 64 + mt * 16 + lr;
#pragma unroll
        for (int nt = 0; nt < 4; nt++) {
            int col = bcol + warpN * 32 + nt * 8 + 2 * lc;
            float x0 = acc[mt][nt][0], x1 = acc[mt][nt][1];
            float x2 = acc[mt][nt][2], x3 = acc[mt][nt][3];
            if (EPI == 1) {
                x0 = 0.5f * x0 * (1.0f + erff(x0 * 0.70710678118654752440f));
                x1 = 0.5f * x1 * (1.0f + erff(x1 * 0.70710678118654752440f));
                x2 = 0.5f * x2 * (1.0f + erff(x2 * 0.70710678118654752440f));
                x3 = 0.5f * x3 * (1.0f + erff(x3 * 0.70710678118654752440f));
            }
            if (r0 < M)     *(float2*)&C[(size_t)r0 * N + col]       = make_float2(x0, x1);
            if (r0 + 8 < M) *(float2*)&C[(size_t)(r0 + 8) * N + col] = make_float2(x2, x3);
        }
    }
}

// ---------------- growth scan ----------------
__global__ void k_growth_scan(const float* __restrict__ sw,
                              const float* __restrict__ z0,
                              const float* __restrict__ v0) {
    int b = blockIdx.x;
    int hd = threadIdx.x;
    int h = hd >> 6;
    float w = 1.0f / (1.0f + expf(-sw[h]));
    float omw = 1.0f - w;
    float prev = z0[hd];
    float s = v0[hd];
    g_smcat[(size_t)b * (Tt + 1) * Dd + hd] = s;
    const float* vp = g_v + (size_t)b * Tt * Dd + hd;
    float* op = g_smcat + (size_t)b * (Tt + 1) * Dd + Dd + hd;
    for (int t = 0; t < Tt; t++) {
        float val = vp[(size_t)t * Dd];
        float diff = val - prev;
        prev = val;
        s = fmaf(w, s, omw * diff);
        op[(size_t)t * Dd] = s;
    }
}

// ---------------- LayerNorm ----------------
__device__ __forceinline__ float wred(float v) {
#pragma unroll
    for (int o = 16; o > 0; o >>= 1) v += __shfl_xor_sync(0xffffffffu, v, o);
    return v;
}

template <int MODE>
__global__ void k_ln(const float* __restrict__ A, const float* __restrict__ Bm,
                     const float* __restrict__ gg, const float* __restrict__ bb,
                     float* __restrict__ out) {
    int r = blockIdx.x;
    int tid = threadIdx.x;
    const float* arow = A + (size_t)r * Dd;
    const float* brow;
    if (MODE == 0) {
        int b = r >> 10, t = r & 1023;
        brow = Bm + ((size_t)b * (Tt + 1) + t + 1) * Dd;
    } else {
        brow = Bm + (size_t)r * Dd;
    }
    int c0 = tid * 4;
    float4 a = *(const float4*)(arow + c0);
    float4 c = *(const float4*)(brow + c0);
    float x0, x1, x2, x3;
    if (MODE == 0) { x0 = a.x - c.x; x1 = a.y - c.y; x2 = a.z - c.z; x3 = a.w - c.w; }
    else           { x0 = a.x + c.x; x1 = a.y + c.y; x2 = a.z + c.z; x3 = a.w + c.w; }

    __shared__ float red[8];
    float s = x0 + x1 + x2 + x3;
    s = wred(s);
    int wid = tid >> 5, lane = tid & 31;
    if (!lane) red[wid] = s;
    __syncthreads();
    float mu = (red[0] + red[1] + red[2] + red[3]) * (1.0f / 512.0f);
    float d0 = x0 - mu, d1 = x1 - mu, d2 = x2 - mu, d3 = x3 - mu;
    float q = d0 * d0 + d1 * d1 + d2 * d2 + d3 * d3;
    q = wred(q);
    if (!lane) red[4 + wid] = q;
    __syncthreads();
    float var = (red[4] + red[5] + red[6] + red[7]) * (1.0f / 512.0f);
    float inv = rsqrtf(var + 1e-5f);
    float4 g4 = *(const float4*)(gg + c0);
    float4 b4 = *(const float4*)(bb + c0);
    float4 o4;
    o4.x = d0 * inv * g4.x + b4.x;
    o4.y = d1 * inv * g4.y + b4.y;
    o4.z = d2 * inv * g4.z + b4.z;
    o4.w = d3 * inv * g4.w + b4.w;
    *(float4*)(out + (size_t)r * Dd + c0) = o4;
}

// ---------------- small prediction GEMM ----------------
__global__ void k_pred(const float* __restrict__ A, int rows_per_b,
                       const float* __restrict__ W, float* __restrict__ out) {
    __shared__ float ws[Dd * CO];
    int tid = threadIdx.x;
    for (int i = tid; i < Dd * CO; i += 256) ws[i] = W[i];
    __syncthreads();
    int r = blockIdx.x * 256 + tid;
    int b = r >> 10, t = r & 1023;
    const float* a = A + ((size_t)b * rows_per_b + t) * Dd;
    float acc[CO];
#pragma unroll
    for (int c = 0; c < CO; c++) acc[c] = 0.f;
    for (int k = 0; k < Dd; k += 4) {
        float4 av = *(const float4*)(a + k);
#pragma unroll
        for (int c = 0; c < CO; c++) {
            acc[c] = fmaf(av.x, ws[(k + 0) * CO + c], acc[c]);
            acc[c] = fmaf(av.y, ws[(k + 1) * CO + c], acc[c]);
            acc[c] = fmaf(av.z, ws[(k + 2) * CO + c], acc[c]);
            acc[c] = fmaf(av.w, ws[(k + 3) * CO + c], acc[c]);
        }
    }
    float* o = out + (size_t)r * CO;
#pragma unroll
    for (int c = 0; c < CO; c++) o[c] = acc[c];
}

// ---------------- level scan ----------------
__global__ void k_level(const float* __restrict__ level,
                        const float* __restrict__ lsw,
                        const float* __restrict__ lv0,
                        float* __restrict__ out) {
    int tid = threadIdx.x;
    if (tid >= Bq * CO) return;
    int b = tid / CO, c = tid % CO;
    float w = 1.0f / (1.0f + expf(-lsw[c]));
    float omw = 1.0f - w;
    float s = lv0[c];
    float a = 0.f;
    const float* lp = level + (size_t)b * Tt * CO + c;
    const float* gp = g_gp + (size_t)b * Tt * CO + c;
    const float* sp = g_sp + (size_t)b * Tt * CO + c;
    float* op = out + (size_t)b * Tt * CO + c;
    for (int t = 0; t < Tt; t++) {
        float val = lp[t * CO] - sp[t * CO];
        s = fmaf(w, s, omw * val);
        a = w * (a + gp[t * CO]);
        op[t * CO] = s + a;
    }
}

extern "C" void kernel_launch(void* const* d_in, const int* in_sizes, int n_in,
                              void* d_out, int out_size) {
    const float* res   = (const float*)d_in[0];
    const float* level = (const float*)d_in[1];
    const float* in_w  = (const float*)d_in[2];
    const float* out_w = (const float*)d_in[3];
    const float* z0    = (const float*)d_in[4];
    const float* gsw   = (const float*)d_in[5];
    const float* gv0   = (const float*)d_in[6];
    const float* ffw1  = (const float*)d_in[7];
    const float* ffw2  = (const float*)d_in[8];
    const float* n1g   = (const float*)d_in[9];
    const float* n1b   = (const float*)d_in[10];
    const float* n2g   = (const float*)d_in[11];
    const float* n2b   = (const float*)d_in[12];
    const float* gpw   = (const float*)d_in[13];
    const float* spw   = (const float*)d_in[14];
    const float* lsw   = (const float*)d_in[15];
    const float* lv0   = (const float*)d_in[16];
    float* out = (float*)d_out;

    float *p_res1, *p_v, *p_smcat, *p_res2, *p_ffh, *p_ffy, *p_gp, *p_sp;
    cudaGetSymbolAddress((void**)&p_res1,  g_res1);
    cudaGetSymbolAddress((void**)&p_v,     g_v);
    cudaGetSymbolAddress((void**)&p_smcat, g_smcat);
    cudaGetSymbolAddress((void**)&p_res2,  g_res2);
    cudaGetSymbolAddress((void**)&p_ffh,   g_ffh);
    cudaGetSymbolAddress((void**)&p_ffy,   g_ffy);
    cudaGetSymbolAddress((void**)&p_gp,    g_gp);
    cudaGetSymbolAddress((void**)&p_sp,    g_sp);

    k_twiddle<<<1, 1024>>>();
    k_dft<<<dim3(64, Bq), 512>>>(res);
    k_topk<<<Bq, 512>>>();
    k_season<<<dim3(TP / 16, Bq), 512>>>(res, out + SEAS_OFF, p_res1);

    // v = res1 @ in_proj_w   [16384,512] x [512,512]
    k_mma<0><<<dim3(Dd / 128, Bq * Tt / 128), 256>>>(p_res1, in_w, p_v,
                                                     Bq * Tt, Dd, Dd);
    k_growth_scan<<<Bq, 512>>>(gsw, z0, gv0);
    // growth = smcat @ out_proj_w   [16400,512] x [512,512]
    k_mma<0><<<dim3(Dd / 128, (Bq * (Tt + 1) + 127) / 128), 256>>>(
        p_smcat, out_w, out + GROW_OFF, Bq * (Tt + 1), Dd, Dd);
    k_ln<0><<<Bq * Tt, 128>>>(p_res1, out + GROW_OFF, n1g, n1b, p_res2);
    // ffh = gelu(res2 @ ff_w1)   [16384,512] x [512,2048]
    k_mma<1><<<dim3(LATENT / 128, Bq * Tt / 128), 256>>>(
        p_res2, ffw1, p_ffh, Bq * Tt, LATENT, Dd);
    // ffy = ffh @ ff_w2   [16384,2048] x [2048,512]
    k_mma<0><<<dim3(Dd / 128, Bq * Tt / 128), 256>>>(
        p_ffh, ffw2, p_ffy, Bq * Tt, Dd, LATENT);
    k_ln<1><<<Bq * Tt, 128>>>(p_res2, p_ffy, n2g, n2b, out + RES3_OFF);
    k_pred<<<(Bq * Tt) / 256, 256>>>(out + GROW_OFF, Tt + 1, gpw, p_gp);
    k_pred<<<(Bq * Tt) / 256, 256>>>(out + SEAS_OFF, TP, spw, p_sp);
    k_level<<<1, 128>>>(level, lsw, lv0, out + LVL_OFF);
}